// round 1
// baseline (speedup 1.0000x reference)
#include <cuda_runtime.h>
#include <math.h>

// ---------------------------------------------------------------------------
// AttentionClassificationHead — GB300 fused kernel
// Shapes (fixed by the problem): B=64, N=512, T=6, E=256, H=4, hd=64, BN=32768
//
// Algebra:
//   scores[h,t] = (x[t] . weff[h] + ceff[h]) / 8,  weff[h] = q_h @ Wk_h
//   xbar[h,:]   = sum_t attw[h,t] * x[t]
//   attn[h*64+d]= Wv_h @ xbar[h] + bv          (GEMM1, via WvT)
//   out         = attn @ out_w^T + out_b       (GEMM2, via out_wT)
//   LN, fc1(gelu exact), fc2 dot, zero invalid windows
// ---------------------------------------------------------------------------

__device__ float g_weff[1024];     // [4][256]
__device__ float g_ceff[4];
__device__ float g_WvT[65536];     // [e][o]  = Wv[o][e]
__device__ float g_outwT[65536];   // [e][o2] = out_w[o2][e]
__device__ float g_w1T[32768];     // [e][o3] = w1[o3][e]

// Shared memory float offsets
#define U0   0        // 4096 floats: weff(+ceff) in phase1, weight tile in GEMMs
#define XB0  4096     // 16448 floats: xbar [w][1028]; later bufB [o][17] and bufC at +8192
#define BA0  20544    // 4352 floats: bufA [o][17]
#define MB0  24896    // 16 ints: mask bits per window
#define SFLOATS 24912
#define SMEM_BYTES (SFLOATS * 4)

__device__ __forceinline__ unsigned long long pk2(float a, float b) {
    return ((unsigned long long)__float_as_uint(b) << 32) |
           (unsigned long long)__float_as_uint(a);
}
__device__ __forceinline__ void fma2(unsigned long long& d,
                                     unsigned long long a,
                                     unsigned long long b) {
    asm("fma.rn.f32x2 %0, %1, %2, %0;" : "+l"(d) : "l"(a), "l"(b));
}
__device__ __forceinline__ float gelu_exact(float v) {
    return 0.5f * v * (1.0f + erff(v * 0.70710678118654752f));
}

// ---------------------------------------------------------------------------
// Prep kernel: q = query@Wq^T+bq, weff/ceff, and weight transposes.
// ---------------------------------------------------------------------------
__global__ void ach_prep(const float* __restrict__ query,
                         const float* __restrict__ ipw,
                         const float* __restrict__ ipb,
                         const float* __restrict__ outw,
                         const float* __restrict__ w1) {
    __shared__ float qs[256];
    int tid = threadIdx.x;
    {
        float a = ipb[tid];
        for (int e = 0; e < 256; e++) a += query[e] * ipw[tid * 256 + e];
        qs[tid] = a;
    }
    __syncthreads();
    const int NT = 1024 + 65536 + 65536 + 32768 + 4;
    for (int idx = blockIdx.x * 256 + tid; idx < NT; idx += gridDim.x * 256) {
        if (idx < 1024) {
            int h = idx >> 8, e = idx & 255;
            float s = 0.f;
            for (int d = 0; d < 64; d++)
                s += qs[h * 64 + d] * ipw[(256 + h * 64 + d) * 256 + e];
            g_weff[idx] = s;
        } else if (idx < 1024 + 65536) {
            int j = idx - 1024;
            g_WvT[j] = ipw[(512 + (j & 255)) * 256 + (j >> 8)];
        } else if (idx < 1024 + 131072) {
            int j = idx - (1024 + 65536);
            g_outwT[j] = outw[(j & 255) * 256 + (j >> 8)];
        } else if (idx < 1024 + 131072 + 32768) {
            int j = idx - (1024 + 131072);
            g_w1T[j] = w1[(j & 127) * 256 + (j >> 7)];
        } else {
            int h = idx - (1024 + 131072 + 32768);
            float s = 0.f;
            for (int d = 0; d < 64; d++)
                s += qs[h * 64 + d] * ipb[256 + h * 64 + d];
            g_ceff[h] = s;
        }
    }
}

// ---------------------------------------------------------------------------
// GEMM stage: out[o][w] = act( bias[o] + sum_e in(e,w) * gW[e][o] )
// 256 threads: w = tid&15, og = tid>>4, thread owns O/16 consecutive o.
// Weight tile (4096 floats) staged in smem region U0. f32x2 packed FFMA.
// HS=true: input is xbar laid [w][1028] with head-selected row (GEMM1).
// ---------------------------------------------------------------------------
template <int O, bool HS, bool ACT>
__device__ __forceinline__ void gemm_stage(float* S,
                                           const float* __restrict__ gW,
                                           const float* __restrict__ bias,
                                           const float* in, float* outb) {
    constexpr int OS = O / 16;     // outputs per thread (16 or 8)
    constexpr int EC = 4096 / O;   // e-rows per tile (16 or 32)
    const int tid = threadIdx.x;
    const int w = tid & 15;
    const int og = tid >> 4;
    const int o0 = og * OS;

    unsigned long long acc[OS / 2];
#pragma unroll
    for (int p = 0; p < OS / 2; p++)
        acc[p] = pk2(bias[o0 + 2 * p], bias[o0 + 2 * p + 1]);

    const int hoff = HS ? (w * 1028 + (og >> 2) * 256) : 0;

    for (int ec = 0; ec < 256; ec += EC) {
        __syncthreads();
#pragma unroll
        for (int i = tid * 4; i < 4096; i += 1024)
            *(float4*)&S[U0 + i] = *(const float4*)&gW[ec * O + i];
        __syncthreads();
#pragma unroll
        for (int ee = 0; ee < EC; ee++) {
            const int e = ec + ee;
            float xb = HS ? in[hoff + e] : in[e * 17 + w];
            unsigned long long xb2 = pk2(xb, xb);
            const longlong2* wr = (const longlong2*)&S[U0 + ee * O + o0];
#pragma unroll
            for (int q = 0; q < OS / 4; q++) {
                longlong2 v = wr[q];
                fma2(acc[2 * q],     (unsigned long long)v.x, xb2);
                fma2(acc[2 * q + 1], (unsigned long long)v.y, xb2);
            }
        }
    }
    __syncthreads();
#pragma unroll
    for (int p = 0; p < OS / 2; p++) {
        float lo = __uint_as_float((unsigned)acc[p]);
        float hi = __uint_as_float((unsigned)(acc[p] >> 32));
        if (ACT) { lo = gelu_exact(lo); hi = gelu_exact(hi); }
        outb[(o0 + 2 * p) * 17 + w]     = lo;
        outb[(o0 + 2 * p + 1) * 17 + w] = hi;
    }
}

// ---------------------------------------------------------------------------
// Main kernel: 2048 CTAs x 256 threads, 16 windows per CTA.
// ---------------------------------------------------------------------------
__global__ void __launch_bounds__(256, 2)
ach_main(const float* __restrict__ x, const int* __restrict__ mask,
         const float* __restrict__ ipb, const float* __restrict__ out_b,
         const float* __restrict__ ln_g, const float* __restrict__ ln_b,
         const float* __restrict__ b1, const float* __restrict__ w2,
         const float* __restrict__ b2, float* __restrict__ out) {
    extern __shared__ float S[];
    const int tid = threadIdx.x;
    const int lane = tid & 31;
    const int wid = tid >> 5;
    const int bn0 = blockIdx.x << 4;

    // ---- load weff/ceff into U region ----
    for (int i = tid; i < 1024; i += 256) S[U0 + i] = g_weff[i];
    if (tid < 4) S[U0 + 1024 + tid] = g_ceff[tid];
    __syncthreads();

    // ---- Phase 1: per-warp windows — scores, softmax, xbar ----
#pragma unroll
    for (int rep = 0; rep < 2; rep++) {
        const int w = wid * 2 + rep;
        const long bn = (long)bn0 + w;
        const float4* xp = (const float4*)(x + bn * 1536);
        float4 xa[6], xc[6];
#pragma unroll
        for (int t = 0; t < 6; t++) {
            xa[t] = xp[t * 64 + lane];
            xc[t] = xp[t * 64 + 32 + lane];
        }
        int mv = (lane < 6) ? mask[bn * 6 + lane] : 0;
        unsigned mb = __ballot_sync(0xffffffffu, mv != 0) & 0x3fu;
        if (lane == 0) ((int*)S)[MB0 + w] = (int)mb;

        float aw[4][6];
#pragma unroll
        for (int h = 0; h < 4; h++) {
            const float4* wf = (const float4*)&S[U0 + h * 256];
            float4 wa = wf[lane], wc = wf[32 + lane];
            float ce = S[U0 + 1024 + h];
            float sc[6];
#pragma unroll
            for (int t = 0; t < 6; t++) {
                float p = xa[t].x * wa.x + xa[t].y * wa.y + xa[t].z * wa.z +
                          xa[t].w * wa.w + xc[t].x * wc.x + xc[t].y * wc.y +
                          xc[t].z * wc.z + xc[t].w * wc.w;
#pragma unroll
                for (int o = 16; o > 0; o >>= 1)
                    p += __shfl_xor_sync(0xffffffffu, p, o);
                sc[t] = ((mb >> t) & 1u) ? (p + ce) * 0.125f : -1e9f;
            }
            float m = sc[0];
#pragma unroll
            for (int t = 1; t < 6; t++) m = fmaxf(m, sc[t]);
            float s = 0.f;
#pragma unroll
            for (int t = 0; t < 6; t++) { aw[h][t] = expf(sc[t] - m); s += aw[h][t]; }
            float inv = 1.0f / s;
#pragma unroll
            for (int t = 0; t < 6; t++) aw[h][t] *= inv;
        }
#pragma unroll
        for (int h = 0; h < 4; h++) {
            float4 A = make_float4(0.f, 0.f, 0.f, 0.f);
            float4 C = make_float4(0.f, 0.f, 0.f, 0.f);
#pragma unroll
            for (int t = 0; t < 6; t++) {
                float a = aw[h][t];
                A.x += a * xa[t].x; A.y += a * xa[t].y;
                A.z += a * xa[t].z; A.w += a * xa[t].w;
                C.x += a * xc[t].x; C.y += a * xc[t].y;
                C.z += a * xc[t].z; C.w += a * xc[t].w;
            }
            *(float4*)&S[XB0 + w * 1028 + h * 256 + 4 * lane] = A;
            *(float4*)&S[XB0 + w * 1028 + h * 256 + 128 + 4 * lane] = C;
        }
    }
    __syncthreads();

    // ---- GEMM1: attn0 = xbar * WvT + bv  -> bufA ----
    gemm_stage<256, true, false>(S, g_WvT, ipb + 512, &S[XB0], &S[BA0]);
    // ---- GEMM2: out = attn0 * out_wT + out_b -> bufB (in XB0 region) ----
    gemm_stage<256, false, false>(S, g_outwT, out_b, &S[BA0], &S[XB0]);
    __syncthreads();

    // ---- LayerNorm: bufB -> bufA ----
#pragma unroll
    for (int rep = 0; rep < 2; rep++) {
        const int w = wid * 2 + rep;
        float v[8], s = 0.f, s2 = 0.f;
#pragma unroll
        for (int j = 0; j < 8; j++) {
            float t = S[XB0 + (lane + 32 * j) * 17 + w];
            v[j] = t; s += t; s2 += t * t;
        }
#pragma unroll
        for (int o = 16; o > 0; o >>= 1) {
            s  += __shfl_xor_sync(0xffffffffu, s, o);
            s2 += __shfl_xor_sync(0xffffffffu, s2, o);
        }
        float mu = s * (1.0f / 256.0f);
        float var = s2 * (1.0f / 256.0f) - mu * mu;
        float rstd = rsqrtf(var + 1e-5f);
#pragma unroll
        for (int j = 0; j < 8; j++) {
            int o = lane + 32 * j;
            S[BA0 + o * 17 + w] = (v[j] - mu) * rstd * ln_g[o] + ln_b[o];
        }
    }
    // gemm_stage's leading __syncthreads orders LN writes before reads

    // ---- GEMM3: fc1 + exact GELU -> bufC (XB0 + 8192) ----
    gemm_stage<128, false, true>(S, g_w1T, b1, &S[BA0], &S[XB0 + 8192]);
    __syncthreads();

    // ---- Final dot with w2, zero invalid windows ----
#pragma unroll
    for (int rep = 0; rep < 2; rep++) {
        const int w = wid * 2 + rep;
        float r = 0.f;
#pragma unroll
        for (int j = 0; j < 4; j++) {
            int o = lane + 32 * j;
            r += S[XB0 + 8192 + o * 17 + w] * w2[o];
        }
#pragma unroll
        for (int o = 16; o > 0; o >>= 1)
            r += __shfl_xor_sync(0xffffffffu, r, o);
        if (lane == 0) {
            int mb = ((int*)S)[MB0 + w];
            out[bn0 + w] = mb ? (r + b2[0]) : 0.0f;
        }
    }
}

// ---------------------------------------------------------------------------
extern "C" void kernel_launch(void* const* d_in, const int* in_sizes, int n_in,
                              void* d_out, int out_size) {
    (void)in_sizes; (void)n_in; (void)out_size;
    const float* x    = (const float*)d_in[0];
    const int*   mask = (const int*)d_in[1];
    const float* query= (const float*)d_in[2];
    const float* ipw  = (const float*)d_in[3];
    const float* ipb  = (const float*)d_in[4];
    const float* outw = (const float*)d_in[5];
    const float* outb = (const float*)d_in[6];
    const float* ln_g = (const float*)d_in[7];
    const float* ln_b = (const float*)d_in[8];
    const float* w1   = (const float*)d_in[9];
    const float* b1   = (const float*)d_in[10];
    const float* w2   = (const float*)d_in[11];
    const float* b2   = (const float*)d_in[12];
    float* out = (float*)d_out;

    cudaFuncSetAttribute(ach_main, cudaFuncAttributeMaxDynamicSharedMemorySize,
                         SMEM_BYTES);

    ach_prep<<<80, 256>>>(query, ipw, ipb, outw, w1);
    ach_main<<<2048, 256, SMEM_BYTES>>>(x, mask, ipb, outb, ln_g, ln_b, b1, w2,
                                        b2, out);
}

// round 2
// speedup vs baseline: 1.3212x; 1.3212x over previous
#include <cuda_runtime.h>
#include <math.h>

// ---------------------------------------------------------------------------
// AttentionClassificationHead — GB300 fused kernel, round 2
// B=64, N=512, T=6, E=256, H=4, hd=64, BN=32768
//
// scores[h,t] = (x[t].weff[h] + ceff[h])/8 ; xbar[h]=Σ attw*x[t]
// GEMM1: attn0 = Wv_h @ xbar[h] + bv     GEMM2: out_proj   GEMM3: fc1+gelu
// All GEMMs: 4 windows x 4(2) outputs per thread, f32x2 FFMA, dbuf weight tiles
// ---------------------------------------------------------------------------

typedef unsigned long long ull;

__device__ float g_weff[1024];     // [4][256]
__device__ float g_ceff[4];
__device__ float g_WvT[65536];     // [e][o]  = Wv[o][e]
__device__ float g_outwT[65536];   // [e][o2] = out_w[o2][e]
__device__ float g_w1T[32768];     // [e][o3] = w1[o3][e]

// Shared memory float offsets
#define W0   0        // 4096: weff(+ceff) in phase1, weight tile in GEMMs
#define XB0  4096     // 16512: xbar [16][1032]; reused as bufB / bufD [16][264]
#define BA0  20608    // 4224: bufA [16][264]
#define MB0  24832    // 16 ints
#define SFLOATS 24848
#define SMEM_BYTES (SFLOATS * 4)
#define XST 1032      // xbar row stride (mod 32 == 8 -> conflict-free)
#define BST 264       // stage buffer row stride (mod 32 == 8)

__device__ __forceinline__ ull pk2(float a, float b) {
    ull r;
    asm("mov.b64 %0, {%1, %2};" : "=l"(r) : "f"(a), "f"(b));
    return r;
}
__device__ __forceinline__ void fma2(ull& d, ull a, ull b) {
    asm("fma.rn.f32x2 %0, %1, %2, %0;" : "+l"(d) : "l"(a), "l"(b));
}
__device__ __forceinline__ float lo32(ull v) { return __uint_as_float((unsigned)v); }
__device__ __forceinline__ float hi32(ull v) { return __uint_as_float((unsigned)(v >> 32)); }
__device__ __forceinline__ float gelu_exact(float v) {
    return 0.5f * v * (1.0f + erff(v * 0.70710678118654752f));
}

// ---------------------------------------------------------------------------
// Prep kernel: q = query@Wq^T+bq, weff/ceff, weight transposes.
// ---------------------------------------------------------------------------
__global__ void ach_prep(const float* __restrict__ query,
                         const float* __restrict__ ipw,
                         const float* __restrict__ ipb,
                         const float* __restrict__ outw,
                         const float* __restrict__ w1) {
    __shared__ float qs[256];
    int tid = threadIdx.x;
    {
        float a = ipb[tid];
        for (int e = 0; e < 256; e++) a += query[e] * ipw[tid * 256 + e];
        qs[tid] = a;
    }
    __syncthreads();
    const int NT = 1024 + 65536 + 65536 + 32768 + 4;
    for (int idx = blockIdx.x * 256 + tid; idx < NT; idx += gridDim.x * 256) {
        if (idx < 1024) {
            int h = idx >> 8, e = idx & 255;
            float s = 0.f;
            for (int d = 0; d < 64; d++)
                s += qs[h * 64 + d] * ipw[(256 + h * 64 + d) * 256 + e];
            g_weff[idx] = s;
        } else if (idx < 1024 + 65536) {
            int j = idx - 1024;
            g_WvT[j] = ipw[(512 + (j & 255)) * 256 + (j >> 8)];
        } else if (idx < 1024 + 131072) {
            int j = idx - (1024 + 65536);
            g_outwT[j] = outw[(j & 255) * 256 + (j >> 8)];
        } else if (idx < 1024 + 131072 + 32768) {
            int j = idx - (1024 + 131072);
            g_w1T[j] = w1[(j & 127) * 256 + (j >> 7)];
        } else {
            int h = idx - (1024 + 131072 + 32768);
            float s = 0.f;
            for (int d = 0; d < 64; d++)
                s += qs[h * 64 + d] * ipb[256 + h * 64 + d];
            g_ceff[h] = s;
        }
    }
}

// ---------------------------------------------------------------------------
// GEMM stage with 4x(OT) register blocking, double-buffered weight tiles.
//   out[w][o] = act( bias[o] + sum_e in(w,e) * gW[e][o] )
// Thread: wg = tid&3 -> windows {wg, wg+4, wg+8, wg+12}; og = tid>>2 -> OT
// consecutive outputs at o0 = og*OT.
// HS: input is xbar [w][XST] with per-output head offset h*256 (h = og>>4).
// ---------------------------------------------------------------------------
template <int O, bool HS, bool ACT>
__device__ __forceinline__ void gemm_stage(float* S,
                                           const float* __restrict__ gW,
                                           const float* __restrict__ bias,
                                           const float* in, int inst,
                                           float* outb) {
    constexpr int OT = O / 64;     // 4 (O=256) or 2 (O=128)
    constexpr int EC = 4096 / O;   // 16 or 32 e-rows per tile
    const int tid = threadIdx.x;
    const int wg = tid & 3;
    const int og = tid >> 2;
    const int o0 = og * OT;

    ull acc[4][OT / 2];
#pragma unroll
    for (int p = 0; p < OT / 2; p++) {
        ull b = pk2(bias[o0 + 2 * p], bias[o0 + 2 * p + 1]);
#pragma unroll
        for (int i = 0; i < 4; i++) acc[i][p] = b;
    }

    const float* xin[4];
#pragma unroll
    for (int i = 0; i < 4; i++)
        xin[i] = in + (wg + 4 * i) * inst + (HS ? (og >> 4) * 256 : 0);

    // prefetch tile 0 into registers
    float4 wreg[4];
#pragma unroll
    for (int r = 0; r < 4; r++)
        wreg[r] = *(const float4*)&gW[tid * 4 + r * 1024];

    for (int ec = 0; ec < 256; ec += EC) {
        __syncthreads();
#pragma unroll
        for (int r = 0; r < 4; r++)
            *(float4*)&S[W0 + tid * 4 + r * 1024] = wreg[r];
        __syncthreads();
        if (ec + EC < 256) {
#pragma unroll
            for (int r = 0; r < 4; r++)
                wreg[r] = *(const float4*)&gW[(ec + EC) * O + tid * 4 + r * 1024];
        }
#pragma unroll
        for (int ee = 0; ee < EC; ee += 4) {
            float4 xv[4];
#pragma unroll
            for (int i = 0; i < 4; i++)
                xv[i] = *(const float4*)&xin[i][ec + ee];
#pragma unroll
            for (int j = 0; j < 4; j++) {
                if (OT == 4) {
                    longlong2 wv = *(const longlong2*)&S[W0 + (ee + j) * O + o0];
#pragma unroll
                    for (int i = 0; i < 4; i++) {
                        float xs = (j == 0) ? xv[i].x : (j == 1) ? xv[i].y
                                 : (j == 2) ? xv[i].z : xv[i].w;
                        ull x2 = pk2(xs, xs);
                        fma2(acc[i][0], (ull)wv.x, x2);
                        fma2(acc[i][1], (ull)wv.y, x2);
                    }
                } else {
                    ull wv = *(const ull*)&S[W0 + (ee + j) * O + o0];
#pragma unroll
                    for (int i = 0; i < 4; i++) {
                        float xs = (j == 0) ? xv[i].x : (j == 1) ? xv[i].y
                                 : (j == 2) ? xv[i].z : xv[i].w;
                        ull x2 = pk2(xs, xs);
                        fma2(acc[i][0], wv, x2);
                    }
                }
            }
        }
    }
    __syncthreads();
#pragma unroll
    for (int i = 0; i < 4; i++) {
        const int w = wg + 4 * i;
        if (OT == 4) {
            float a = lo32(acc[i][0]), b = hi32(acc[i][0]);
            float c = lo32(acc[i][1]), d = hi32(acc[i][1]);
            if (ACT) { a = gelu_exact(a); b = gelu_exact(b);
                       c = gelu_exact(c); d = gelu_exact(d); }
            *(float4*)&outb[w * BST + o0] = make_float4(a, b, c, d);
        } else {
            float a = lo32(acc[i][0]), b = hi32(acc[i][0]);
            if (ACT) { a = gelu_exact(a); b = gelu_exact(b); }
            *(float2*)&outb[w * BST + o0] = make_float2(a, b);
        }
    }
}

// ---------------------------------------------------------------------------
// Main kernel: 2048 CTAs x 256 threads, 16 windows per CTA.
// ---------------------------------------------------------------------------
__global__ void __launch_bounds__(256, 2)
ach_main(const float* __restrict__ x, const int* __restrict__ mask,
         const float* __restrict__ ipb, const float* __restrict__ out_b,
         const float* __restrict__ ln_g, const float* __restrict__ ln_b,
         const float* __restrict__ b1, const float* __restrict__ w2,
         const float* __restrict__ b2, float* __restrict__ out) {
    extern __shared__ float S[];
    const int tid = threadIdx.x;
    const int lane = tid & 31;
    const int wid = tid >> 5;
    const int bn0 = blockIdx.x << 4;

    // ---- load weff/ceff into W0 region ----
    for (int i = tid; i < 1024; i += 256) S[W0 + i] = g_weff[i];
    if (tid < 4) S[W0 + 1024 + tid] = g_ceff[tid];
    __syncthreads();

    // ---- Phase 1: per-warp windows — scores, softmax, xbar ----
#pragma unroll
    for (int rep = 0; rep < 2; rep++) {
        const int w = wid * 2 + rep;
        const long bn = (long)bn0 + w;
        const float4* xp = (const float4*)(x + bn * 1536);
        float4 xa[6], xc[6];
#pragma unroll
        for (int t = 0; t < 6; t++) {
            xa[t] = xp[t * 64 + lane];
            xc[t] = xp[t * 64 + 32 + lane];
        }
        int mv = (lane < 6) ? mask[bn * 6 + lane] : 0;
        unsigned mb = __ballot_sync(0xffffffffu, mv != 0) & 0x3fu;
        if (lane == 0) ((int*)S)[MB0 + w] = (int)mb;

        float aw[4][6];
#pragma unroll
        for (int h = 0; h < 4; h++) {
            const float4* wf = (const float4*)&S[W0 + h * 256];
            float4 wa = wf[lane], wc = wf[32 + lane];
            float ce = S[W0 + 1024 + h];
            float sc[6];
#pragma unroll
            for (int t = 0; t < 6; t++) {
                float p = xa[t].x * wa.x + xa[t].y * wa.y + xa[t].z * wa.z +
                          xa[t].w * wa.w + xc[t].x * wc.x + xc[t].y * wc.y +
                          xc[t].z * wc.z + xc[t].w * wc.w;
#pragma unroll
                for (int o = 16; o > 0; o >>= 1)
                    p += __shfl_xor_sync(0xffffffffu, p, o);
                sc[t] = ((mb >> t) & 1u) ? (p + ce) * 0.125f : -1e9f;
            }
            float m = sc[0];
#pragma unroll
            for (int t = 1; t < 6; t++) m = fmaxf(m, sc[t]);
            float s = 0.f;
#pragma unroll
            for (int t = 0; t < 6; t++) { aw[h][t] = expf(sc[t] - m); s += aw[h][t]; }
            float inv = 1.0f / s;
#pragma unroll
            for (int t = 0; t < 6; t++) aw[h][t] *= inv;
        }
#pragma unroll
        for (int h = 0; h < 4; h++) {
            float4 A = make_float4(0.f, 0.f, 0.f, 0.f);
            float4 C = make_float4(0.f, 0.f, 0.f, 0.f);
#pragma unroll
            for (int t = 0; t < 6; t++) {
                float a = aw[h][t];
                A.x += a * xa[t].x; A.y += a * xa[t].y;
                A.z += a * xa[t].z; A.w += a * xa[t].w;
                C.x += a * xc[t].x; C.y += a * xc[t].y;
                C.z += a * xc[t].z; C.w += a * xc[t].w;
            }
            *(float4*)&S[XB0 + w * XST + h * 256 + 4 * lane] = A;
            *(float4*)&S[XB0 + w * XST + h * 256 + 128 + 4 * lane] = C;
        }
    }
    __syncthreads();

    // ---- GEMM1: attn0 = xbar * WvT + bv  -> bufA ----
    gemm_stage<256, true, false>(S, g_WvT, ipb + 512, &S[XB0], XST, &S[BA0]);
    // ---- GEMM2: out = attn0 * out_wT + out_b -> bufB (XB0 region) ----
    gemm_stage<256, false, false>(S, g_outwT, out_b, &S[BA0], BST, &S[XB0]);
    __syncthreads();

    // ---- LayerNorm: bufB -> bufA ----
#pragma unroll
    for (int rep = 0; rep < 2; rep++) {
        const int w = wid * 2 + rep;
        float v[8], s = 0.f, s2 = 0.f;
#pragma unroll
        for (int j = 0; j < 8; j++) {
            float t = S[XB0 + w * BST + lane + 32 * j];
            v[j] = t; s += t; s2 += t * t;
        }
#pragma unroll
        for (int o = 16; o > 0; o >>= 1) {
            s  += __shfl_xor_sync(0xffffffffu, s, o);
            s2 += __shfl_xor_sync(0xffffffffu, s2, o);
        }
        float mu = s * (1.0f / 256.0f);
        float var = s2 * (1.0f / 256.0f) - mu * mu;
        float rstd = rsqrtf(var + 1e-5f);
#pragma unroll
        for (int j = 0; j < 8; j++) {
            int o = lane + 32 * j;
            S[BA0 + w * BST + o] = (v[j] - mu) * rstd * ln_g[o] + ln_b[o];
        }
    }
    // gemm_stage's leading __syncthreads orders LN writes before reads

    // ---- GEMM3: fc1 + exact GELU -> bufD (XB0 region) ----
    gemm_stage<128, false, true>(S, g_w1T, b1, &S[BA0], BST, &S[XB0]);
    __syncthreads();

    // ---- Final dot with w2, zero invalid windows ----
#pragma unroll
    for (int rep = 0; rep < 2; rep++) {
        const int w = wid * 2 + rep;
        float r = 0.f;
#pragma unroll
        for (int j = 0; j < 4; j++) {
            int o = lane + 32 * j;
            r += S[XB0 + w * BST + o] * w2[o];
        }
#pragma unroll
        for (int o = 16; o > 0; o >>= 1)
            r += __shfl_xor_sync(0xffffffffu, r, o);
        if (lane == 0) {
            int mb = ((int*)S)[MB0 + w];
            out[bn0 + w] = mb ? (r + b2[0]) : 0.0f;
        }
    }
}

// ---------------------------------------------------------------------------
extern "C" void kernel_launch(void* const* d_in, const int* in_sizes, int n_in,
                              void* d_out, int out_size) {
    (void)in_sizes; (void)n_in; (void)out_size;
    const float* x    = (const float*)d_in[0];
    const int*   mask = (const int*)d_in[1];
    const float* query= (const float*)d_in[2];
    const float* ipw  = (const float*)d_in[3];
    const float* ipb  = (const float*)d_in[4];
    const float* outw = (const float*)d_in[5];
    const float* outb = (const float*)d_in[6];
    const float* ln_g = (const float*)d_in[7];
    const float* ln_b = (const float*)d_in[8];
    const float* w1   = (const float*)d_in[9];
    const float* b1   = (const float*)d_in[10];
    const float* w2   = (const float*)d_in[11];
    const float* b2   = (const float*)d_in[12];
    float* out = (float*)d_out;

    cudaFuncSetAttribute(ach_main, cudaFuncAttributeMaxDynamicSharedMemorySize,
                         SMEM_BYTES);

    ach_prep<<<80, 256>>>(query, ipw, ipb, outw, w1);
    ach_main<<<2048, 256, SMEM_BYTES>>>(x, mask, ipb, outb, ln_g, ln_b, b1, w2,
                                        b2, out);
}

// round 3
// speedup vs baseline: 1.8950x; 1.4342x over previous
#include <cuda_runtime.h>
#include <cuda_bf16.h>
#include <math.h>

// ---------------------------------------------------------------------------
// AttentionClassificationHead — GB300, round 3: bf16-split tensor-core GEMMs
// B=64, N=512, T=6, E=256, H=4, hd=64, BN=32768; 32 windows per CTA.
// ---------------------------------------------------------------------------

__device__ float g_weff[1024];       // [4][256]
__device__ float g_ceff[4];
// Weight fragments: uint2 = (hi bf16 pair, lo bf16 pair) for k={2k2, 2k2+1}
__device__ uint2 g_B1[34816];        // [4 heads][128 k2][68]  (n<64 valid)
__device__ uint2 g_B2[33280];        // [128 k2][260]          (n<256 valid)
__device__ uint2 g_B3[16896];        // [128 k2][132]          (n<128 valid)

// Shared memory float offsets
#define W0   0            // 1028: weff + ceff (phase 1 only)
#define XB0  1056         // 32*1032 = 33024: xbar fp32; later bufB [32][264]
#define BA0  34080        // 32*264 = 8448: bufA
#define BB0  XB0
#define MB0  42528        // 32 ints
#define SFLOATS 42560
#define SMEM_BYTES (SFLOATS * 4)
#define XST 1032
#define BST 264

__device__ __forceinline__ float gelu_exact(float v) {
    return 0.5f * v * (1.0f + erff(v * 0.70710678118654752f));
}

// rn split of a float2 into hi/lo bf16x2 (low half = .x / even k)
__device__ __forceinline__ void split2(float2 v, unsigned& hi, unsigned& lo) {
    asm("cvt.rn.bf16x2.f32 %0, %1, %2;" : "=r"(hi) : "f"(v.y), "f"(v.x));
    float lx = v.x - __uint_as_float(hi << 16);
    float ly = v.y - __uint_as_float(hi & 0xffff0000u);
    asm("cvt.rn.bf16x2.f32 %0, %1, %2;" : "=r"(lo) : "f"(ly), "f"(lx));
}

__device__ __forceinline__ void mma16816(float* c, const unsigned* a,
                                         unsigned b0, unsigned b1) {
    asm("mma.sync.aligned.m16n8k16.row.col.f32.bf16.bf16.f32 "
        "{%0,%1,%2,%3}, {%4,%5,%6,%7}, {%8,%9}, {%0,%1,%2,%3};"
        : "+f"(c[0]), "+f"(c[1]), "+f"(c[2]), "+f"(c[3])
        : "r"(a[0]), "r"(a[1]), "r"(a[2]), "r"(a[3]), "r"(b0), "r"(b1));
}

// ---------------------------------------------------------------------------
// Prep: weff/ceff + split-bf16 fragment-packed weights.
// ---------------------------------------------------------------------------
__device__ __forceinline__ uint2 split_pack(float f0, float f1) {
    __nv_bfloat16 h0 = __float2bfloat16(f0);
    __nv_bfloat16 h1 = __float2bfloat16(f1);
    __nv_bfloat16 l0 = __float2bfloat16(f0 - __bfloat162float(h0));
    __nv_bfloat16 l1 = __float2bfloat16(f1 - __bfloat162float(h1));
    uint2 r;
    r.x = ((unsigned)__bfloat16_as_ushort(h1) << 16) | __bfloat16_as_ushort(h0);
    r.y = ((unsigned)__bfloat16_as_ushort(l1) << 16) | __bfloat16_as_ushort(l0);
    return r;
}

__global__ void ach_prep(const float* __restrict__ query,
                         const float* __restrict__ ipw,
                         const float* __restrict__ ipb,
                         const float* __restrict__ outw,
                         const float* __restrict__ w1) {
    __shared__ float qs[256];
    int tid = threadIdx.x;
    {
        float a = ipb[tid];
        for (int e = 0; e < 256; e++) a += query[e] * ipw[tid * 256 + e];
        qs[tid] = a;
    }
    __syncthreads();
    const int N1 = 1024, N2 = N1 + 34816, N3 = N2 + 33280, N4 = N3 + 16896;
    const int NT = N4 + 4;
    for (int idx = blockIdx.x * 256 + tid; idx < NT; idx += gridDim.x * 256) {
        if (idx < N1) {
            int h = idx >> 8, e = idx & 255;
            float s = 0.f;
            for (int d = 0; d < 64; d++)
                s += qs[h * 64 + d] * ipw[(256 + h * 64 + d) * 256 + e];
            g_weff[idx] = s;
        } else if (idx < N2) {
            int j = idx - N1;
            int h = j / 8704, r = j % 8704, k2 = r / 68, n = r % 68;
            uint2 v = make_uint2(0u, 0u);
            if (n < 64) {
                const float* src = ipw + (512 + h * 64 + n) * 256 + 2 * k2;
                v = split_pack(src[0], src[1]);
            }
            g_B1[j] = v;
        } else if (idx < N3) {
            int j = idx - N2, k2 = j / 260, n = j % 260;
            uint2 v = make_uint2(0u, 0u);
            if (n < 256) {
                const float* src = outw + n * 256 + 2 * k2;
                v = split_pack(src[0], src[1]);
            }
            g_B2[j] = v;
        } else if (idx < N4) {
            int j = idx - N3, k2 = j / 132, n = j % 132;
            uint2 v = make_uint2(0u, 0u);
            if (n < 128) {
                const float* src = w1 + n * 256 + 2 * k2;
                v = split_pack(src[0], src[1]);
            }
            g_B3[j] = v;
        } else {
            int h = idx - N4;
            float s = 0.f;
            for (int d = 0; d < 64; d++)
                s += qs[h * 64 + d] * ipb[256 + h * 64 + d];
            g_ceff[h] = s;
        }
    }
}

// ---------------------------------------------------------------------------
// MMA GEMM stage: per warp, M=32 (2 m16 tiles) x (NT*8 cols) x K=256.
// A: fp32 in smem (split on the fly). B: split-bf16 fragments LDG'd from L2,
// double-buffered one k-tile ahead. Out: fp32 smem [32][264].
// ---------------------------------------------------------------------------
template <int NT, bool ACT>
__device__ __forceinline__ void gemm_mma(const float* __restrict__ Asm, int Ast,
                                         int koff,
                                         const uint2* __restrict__ Bg, int Bst,
                                         int ncol0,
                                         const float* __restrict__ bias,
                                         int obase,
                                         float* __restrict__ outsm) {
    const int lane = threadIdx.x & 31;
    const int g = lane >> 2, t = lane & 3;

    float acc[2][NT][4];
#pragma unroll
    for (int nt = 0; nt < NT; nt++) {
        float b0 = bias[obase + nt * 8 + 2 * t];
        float b1 = bias[obase + nt * 8 + 2 * t + 1];
#pragma unroll
        for (int mi = 0; mi < 2; mi++) {
            acc[mi][nt][0] = b0; acc[mi][nt][1] = b1;
            acc[mi][nt][2] = b0; acc[mi][nt][3] = b1;
        }
    }

    const uint2* Bp = Bg + t * Bst + ncol0 + g;
    uint2 Bc[NT][2], Bn[NT][2];
#pragma unroll
    for (int nt = 0; nt < NT; nt++) {
        Bc[nt][0] = __ldg(Bp + nt * 8);
        Bc[nt][1] = __ldg(Bp + nt * 8 + 4 * Bst);
    }

#pragma unroll
    for (int kt = 0; kt < 16; kt++) {
        if (kt < 15) {
            const uint2* Bk = Bp + (kt + 1) * 8 * Bst;
#pragma unroll
            for (int nt = 0; nt < NT; nt++) {
                Bn[nt][0] = __ldg(Bk + nt * 8);
                Bn[nt][1] = __ldg(Bk + nt * 8 + 4 * Bst);
            }
        }
        unsigned Ah[2][4], Al[2][4];
#pragma unroll
        for (int mi = 0; mi < 2; mi++) {
            const float* Ar = Asm + (mi * 16 + g) * Ast + koff + kt * 16 + 2 * t;
            split2(*(const float2*)Ar,                 Ah[mi][0], Al[mi][0]);
            split2(*(const float2*)(Ar + 8 * Ast),     Ah[mi][1], Al[mi][1]);
            split2(*(const float2*)(Ar + 8),           Ah[mi][2], Al[mi][2]);
            split2(*(const float2*)(Ar + 8 * Ast + 8), Ah[mi][3], Al[mi][3]);
        }
#pragma unroll
        for (int mi = 0; mi < 2; mi++)
#pragma unroll
            for (int nt = 0; nt < NT; nt++) {
                mma16816(acc[mi][nt], Ah[mi], Bc[nt][0].x, Bc[nt][1].x);
                mma16816(acc[mi][nt], Ah[mi], Bc[nt][0].y, Bc[nt][1].y);
                mma16816(acc[mi][nt], Al[mi], Bc[nt][0].x, Bc[nt][1].x);
            }
#pragma unroll
        for (int nt = 0; nt < NT; nt++) {
            Bc[nt][0] = Bn[nt][0];
            Bc[nt][1] = Bn[nt][1];
        }
    }

#pragma unroll
    for (int mi = 0; mi < 2; mi++)
#pragma unroll
        for (int nt = 0; nt < NT; nt++) {
            float c0 = acc[mi][nt][0], c1 = acc[mi][nt][1];
            float c2 = acc[mi][nt][2], c3 = acc[mi][nt][3];
            if (ACT) {
                c0 = gelu_exact(c0); c1 = gelu_exact(c1);
                c2 = gelu_exact(c2); c3 = gelu_exact(c3);
            }
            int col = obase + nt * 8 + 2 * t;
            *(float2*)&outsm[(mi * 16 + g) * BST + col]     = make_float2(c0, c1);
            *(float2*)&outsm[(mi * 16 + g + 8) * BST + col] = make_float2(c2, c3);
        }
}

// ---------------------------------------------------------------------------
// Main kernel: 1024 CTAs x 256 threads, 32 windows per CTA.
// ---------------------------------------------------------------------------
__global__ void __launch_bounds__(256, 1)
ach_main(const float* __restrict__ x, const int* __restrict__ mask,
         const float* __restrict__ ipb, const float* __restrict__ out_b,
         const float* __restrict__ ln_g, const float* __restrict__ ln_b,
         const float* __restrict__ b1, const float* __restrict__ w2,
         const float* __restrict__ b2, float* __restrict__ out) {
    extern __shared__ float S[];
    const int tid = threadIdx.x;
    const int lane = tid & 31;
    const int wid = tid >> 5;
    const int bn0 = blockIdx.x << 5;

    for (int i = tid; i < 1024; i += 256) S[W0 + i] = g_weff[i];
    if (tid < 4) S[W0 + 1024 + tid] = g_ceff[tid];
    __syncthreads();

    // ---- Phase 1: 4 windows per warp — scores, softmax, xbar ----
#pragma unroll
    for (int rep = 0; rep < 4; rep++) {
        const int w = wid * 4 + rep;
        const long bn = (long)bn0 + w;
        const float4* xp = (const float4*)(x + bn * 1536);
        float4 xa[6], xc[6];
#pragma unroll
        for (int t = 0; t < 6; t++) {
            xa[t] = xp[t * 64 + lane];
            xc[t] = xp[t * 64 + 32 + lane];
        }
        int mv = (lane < 6) ? mask[bn * 6 + lane] : 0;
        unsigned mb = __ballot_sync(0xffffffffu, mv != 0) & 0x3fu;
        if (lane == 0) ((int*)S)[MB0 + w] = (int)mb;

        float aw[4][6];
#pragma unroll
        for (int h = 0; h < 4; h++) {
            const float4* wf = (const float4*)&S[W0 + h * 256];
            float4 wa = wf[lane], wc = wf[32 + lane];
            float ce = S[W0 + 1024 + h];
            float sc[6];
#pragma unroll
            for (int t = 0; t < 6; t++) {
                float p = xa[t].x * wa.x + xa[t].y * wa.y + xa[t].z * wa.z +
                          xa[t].w * wa.w + xc[t].x * wc.x + xc[t].y * wc.y +
                          xc[t].z * wc.z + xc[t].w * wc.w;
#pragma unroll
                for (int o = 16; o > 0; o >>= 1)
                    p += __shfl_xor_sync(0xffffffffu, p, o);
                sc[t] = ((mb >> t) & 1u) ? (p + ce) * 0.125f : -1e9f;
            }
            float m = sc[0];
#pragma unroll
            for (int t = 1; t < 6; t++) m = fmaxf(m, sc[t]);
            float s = 0.f;
#pragma unroll
            for (int t = 0; t < 6; t++) { aw[h][t] = expf(sc[t] - m); s += aw[h][t]; }
            float inv = 1.0f / s;
#pragma unroll
            for (int t = 0; t < 6; t++) aw[h][t] *= inv;
        }
#pragma unroll
        for (int h = 0; h < 4; h++) {
            float4 A = make_float4(0.f, 0.f, 0.f, 0.f);
            float4 C = make_float4(0.f, 0.f, 0.f, 0.f);
#pragma unroll
            for (int t = 0; t < 6; t++) {
                float a = aw[h][t];
                A.x += a * xa[t].x; A.y += a * xa[t].y;
                A.z += a * xa[t].z; A.w += a * xa[t].w;
                C.x += a * xc[t].x; C.y += a * xc[t].y;
                C.z += a * xc[t].z; C.w += a * xc[t].w;
            }
            *(float4*)&S[XB0 + w * XST + h * 256 + 4 * lane] = A;
            *(float4*)&S[XB0 + w * XST + h * 256 + 128 + 4 * lane] = C;
        }
    }
    __syncthreads();

    // ---- GEMM1 (block-diag by head): xbar -> bufA ----
    {
        const int h = wid >> 1, half = wid & 1;
        gemm_mma<4, false>(&S[XB0], XST, h * 256,
                           g_B1 + h * 8704, 68, half * 32,
                           ipb + 512, h * 64 + half * 32, &S[BA0]);
    }
    __syncthreads();
    // ---- GEMM2: bufA -> bufB (overwrites xbar region) ----
    gemm_mma<4, false>(&S[BA0], BST, 0, g_B2, 260, wid * 32,
                       out_b, wid * 32, &S[BB0]);
    __syncthreads();

    // ---- LayerNorm: bufB -> bufA ----
#pragma unroll
    for (int rep = 0; rep < 4; rep++) {
        const int w = wid * 4 + rep;
        float v[8], s = 0.f, s2 = 0.f;
#pragma unroll
        for (int j = 0; j < 8; j++) {
            float t = S[BB0 + w * BST + lane + 32 * j];
            v[j] = t; s += t; s2 += t * t;
        }
#pragma unroll
        for (int o = 16; o > 0; o >>= 1) {
            s  += __shfl_xor_sync(0xffffffffu, s, o);
            s2 += __shfl_xor_sync(0xffffffffu, s2, o);
        }
        float mu = s * (1.0f / 256.0f);
        float var = s2 * (1.0f / 256.0f) - mu * mu;
        float rstd = rsqrtf(var + 1e-5f);
#pragma unroll
        for (int j = 0; j < 8; j++) {
            int o = lane + 32 * j;
            S[BA0 + w * BST + o] = (v[j] - mu) * rstd * ln_g[o] + ln_b[o];
        }
    }
    __syncthreads();

    // ---- GEMM3: fc1 + exact GELU: bufA -> bufB ----
    gemm_mma<2, true>(&S[BA0], BST, 0, g_B3, 132, wid * 16,
                      b1, wid * 16, &S[BB0]);
    __syncthreads();

    // ---- Final dot with w2, zero invalid windows ----
#pragma unroll
    for (int rep = 0; rep < 4; rep++) {
        const int w = wid * 4 + rep;
        float r = 0.f;
#pragma unroll
        for (int j = 0; j < 4; j++) {
            int o = lane + 32 * j;
            r += S[BB0 + w * BST + o] * w2[o];
        }
#pragma unroll
        for (int o = 16; o > 0; o >>= 1)
            r += __shfl_xor_sync(0xffffffffu, r, o);
        if (lane == 0) {
            int mb = ((int*)S)[MB0 + w];
            out[bn0 + w] = mb ? (r + b2[0]) : 0.0f;
        }
    }
}

// ---------------------------------------------------------------------------
extern "C" void kernel_launch(void* const* d_in, const int* in_sizes, int n_in,
                              void* d_out, int out_size) {
    (void)in_sizes; (void)n_in; (void)out_size;
    const float* x    = (const float*)d_in[0];
    const int*   mask = (const int*)d_in[1];
    const float* query= (const float*)d_in[2];
    const float* ipw  = (const float*)d_in[3];
    const float* ipb  = (const float*)d_in[4];
    const float* outw = (const float*)d_in[5];
    const float* outb = (const float*)d_in[6];
    const float* ln_g = (const float*)d_in[7];
    const float* ln_b = (const float*)d_in[8];
    const float* w1   = (const float*)d_in[9];
    const float* b1   = (const float*)d_in[10];
    const float* w2   = (const float*)d_in[11];
    const float* b2   = (const float*)d_in[12];
    float* out = (float*)d_out;

    cudaFuncSetAttribute(ach_main, cudaFuncAttributeMaxDynamicSharedMemorySize,
                         SMEM_BYTES);

    ach_prep<<<80, 256>>>(query, ipw, ipb, outw, w1);
    ach_main<<<1024, 256, SMEM_BYTES>>>(x, mask, ipb, outb, ln_g, ln_b, b1, w2,
                                        b2, out);
}